// round 1
// baseline (speedup 1.0000x reference)
#include <cuda_runtime.h>
#include <math.h>

// ---------------- problem constants ----------------
#define DIMX 1024
#define COND_DIM 512
#define HEADS 32
#define DIM_HEAD 32
#define NTOK 65              // ws*ws + 1 register token
#define B_TOT 512
#define B_IMG 16
#define M_TOK (B_TOT * NTOK) // 33280 = 260 * 128
#define TWO_DIM (2 * DIMX)

// ---------------- scratch (device globals; no runtime alloc allowed) ----------------
__device__ float g_h1[B_IMG * TWO_DIM];                   // FiLM hidden
__device__ float g_gb[B_IMG * TWO_DIM];                   // gamma|beta
__device__ float g_xn[(size_t)M_TOK * DIMX];              // modulated layernorm output
__device__ float g_qkv[(size_t)M_TOK * 3 * DIMX];         // qkv projection
__device__ float g_o[(size_t)M_TOK * DIMX];               // attention output (pre w_out)

// ---------------- FiLM MLP ----------------
__global__ __launch_bounds__(256) void film1_kernel(
    const float* __restrict__ cond, const float* __restrict__ w1,
    const float* __restrict__ b1)
{
    int j = blockIdx.x * 256 + threadIdx.x;   // 0..2047
    int i = blockIdx.y;                       // 0..15
    const float* c = cond + i * COND_DIM;
    float acc = b1[j];
    #pragma unroll 4
    for (int k = 0; k < COND_DIM; k++)
        acc = fmaf(c[k], w1[k * TWO_DIM + j], acc);
    // silu
    g_h1[i * TWO_DIM + j] = acc / (1.f + __expf(-acc));
}

__global__ __launch_bounds__(256) void film2_kernel(
    const float* __restrict__ w2, const float* __restrict__ b2)
{
    int j = blockIdx.x * 256 + threadIdx.x;
    int i = blockIdx.y;
    const float* h = g_h1 + i * TWO_DIM;
    float acc = b2[j];
    #pragma unroll 4
    for (int k = 0; k < TWO_DIM; k++)
        acc = fmaf(h[k], w2[k * TWO_DIM + j], acc);
    g_gb[i * TWO_DIM + j] = acc;
}

// ---------------- LayerNorm + FiLM modulation ----------------
__global__ __launch_bounds__(256) void ln_film_kernel(const float* __restrict__ x)
{
    int row = blockIdx.x;                  // token row 0..33279
    int img = (row / NTOK) >> 5;           // b / 32  (d_rep = 512/16)
    const float4* xr = (const float4*)(x + (size_t)row * DIMX);
    int t = threadIdx.x;                   // 256 threads, 4 floats each
    float4 v = xr[t];
    float s  = v.x + v.y + v.z + v.w;
    float ss = v.x*v.x + v.y*v.y + v.z*v.z + v.w*v.w;

    __shared__ float red_s[8], red_ss[8];
    #pragma unroll
    for (int o = 16; o > 0; o >>= 1) {
        s  += __shfl_down_sync(0xffffffffu, s, o);
        ss += __shfl_down_sync(0xffffffffu, ss, o);
    }
    int warp = t >> 5, lane = t & 31;
    if (lane == 0) { red_s[warp] = s; red_ss[warp] = ss; }
    __syncthreads();
    if (warp == 0) {
        s  = (lane < 8) ? red_s[lane]  : 0.f;
        ss = (lane < 8) ? red_ss[lane] : 0.f;
        #pragma unroll
        for (int o = 4; o > 0; o >>= 1) {
            s  += __shfl_down_sync(0xffffffffu, s, o);
            ss += __shfl_down_sync(0xffffffffu, ss, o);
        }
        if (lane == 0) { red_s[0] = s; red_ss[0] = ss; }
    }
    __syncthreads();
    float mu  = red_s[0] * (1.f / DIMX);
    float var = red_ss[0] * (1.f / DIMX) - mu * mu;
    float rs  = rsqrtf(var + 1e-5f);

    const float4* gam = (const float4*)(g_gb + (size_t)img * TWO_DIM);
    const float4* bet = (const float4*)(g_gb + (size_t)img * TWO_DIM + DIMX);
    float4 gv = gam[t], bv = bet[t];
    float4 o;
    o.x = fmaf((v.x - mu) * rs, gv.x, bv.x);
    o.y = fmaf((v.y - mu) * rs, gv.y, bv.y);
    o.z = fmaf((v.z - mu) * rs, gv.z, bv.z);
    o.w = fmaf((v.w - mu) * rs, gv.w, bv.w);
    ((float4*)(g_xn + (size_t)row * DIMX))[t] = o;
}

// ---------------- tiled fp32 SGEMM: C[M,N] = A[M,K] @ B[K,N] ----------------
// All dims divide tiles exactly for our shapes (M=33280, N in {3072,1024}, K in {1024}).
#define BM 128
#define BN 128
#define BKK 8
#define TM 8
#define TN 8

__global__ __launch_bounds__(256) void sgemm_kernel(
    const float* __restrict__ A, const float* __restrict__ B,
    float* __restrict__ C, int M, int N, int K)
{
    __shared__ float As[BKK][BM];
    __shared__ float Bs[BKK][BN];
    const int tid  = threadIdx.x;
    const int trow = tid >> 4;            // 0..15
    const int tcol = tid & 15;            // 0..15
    const int row0 = blockIdx.y * BM;
    const int col0 = blockIdx.x * BN;

    const int a_row = tid >> 1;           // 0..127
    const int a_col = (tid & 1) << 2;     // 0 or 4
    const int b_row = tid >> 5;           // 0..7
    const int b_col = (tid & 31) << 2;    // 0..124

    const float* Aptr = A + (size_t)(row0 + a_row) * K + a_col;
    const float* Bptr = B + (size_t)b_row * N + col0 + b_col;

    float acc[TM][TN];
    #pragma unroll
    for (int i = 0; i < TM; i++)
        #pragma unroll
        for (int j = 0; j < TN; j++) acc[i][j] = 0.f;

    for (int k0 = 0; k0 < K; k0 += BKK) {
        float4 av = *(const float4*)(Aptr + k0);
        As[a_col + 0][a_row] = av.x;
        As[a_col + 1][a_row] = av.y;
        As[a_col + 2][a_row] = av.z;
        As[a_col + 3][a_row] = av.w;
        *(float4*)&Bs[b_row][b_col] = *(const float4*)(Bptr + (size_t)k0 * N);
        __syncthreads();
        #pragma unroll
        for (int kk = 0; kk < BKK; kk++) {
            float ar[TM], br[TN];
            #pragma unroll
            for (int i = 0; i < TM; i += 4)
                *(float4*)&ar[i] = *(const float4*)&As[kk][trow * TM + i];
            #pragma unroll
            for (int j = 0; j < TN; j += 4)
                *(float4*)&br[j] = *(const float4*)&Bs[kk][tcol * TN + j];
            #pragma unroll
            for (int i = 0; i < TM; i++)
                #pragma unroll
                for (int j = 0; j < TN; j++)
                    acc[i][j] = fmaf(ar[i], br[j], acc[i][j]);
        }
        __syncthreads();
    }
    #pragma unroll
    for (int i = 0; i < TM; i++) {
        float* Crow = C + (size_t)(row0 + trow * TM + i) * N + col0 + tcol * TN;
        *(float4*)(Crow)     = make_float4(acc[i][0], acc[i][1], acc[i][2], acc[i][3]);
        *(float4*)(Crow + 4) = make_float4(acc[i][4], acc[i][5], acc[i][6], acc[i][7]);
    }
}

// ---------------- per-(b,h) attention: rmsnorm(q,k) -> sim+bias -> softmax -> PV ----------------
__global__ __launch_bounds__(256) void attn_kernel(
    const float* __restrict__ q_gamma, const float* __restrict__ k_gamma,
    const float* __restrict__ rel_emb, const int* __restrict__ rel_idx)
{
    int b = blockIdx.x;      // 0..511
    int h = blockIdx.y;      // 0..31

    __shared__ float qs[NTOK][DIM_HEAD];
    __shared__ float ks[NTOK][DIM_HEAD];
    __shared__ float vs[NTOK][DIM_HEAD];
    __shared__ float ps[NTOK][NTOK];
    __shared__ float qg[DIM_HEAD], kg[DIM_HEAD];

    int t = threadIdx.x;     // 256
    if (t < DIM_HEAD) {
        qg[t] = q_gamma[h * DIM_HEAD + t];
        kg[t] = k_gamma[h * DIM_HEAD + t];
    }
    const float* base = g_qkv + (size_t)(b * NTOK) * (3 * DIMX) + h * DIM_HEAD;
    for (int idx = t; idx < NTOK * DIM_HEAD; idx += 256) {
        int n = idx >> 5, d = idx & 31;
        const float* r = base + (size_t)n * (3 * DIMX);
        qs[n][d] = r[d];
        ks[n][d] = r[DIMX + d];
        vs[n][d] = r[2 * DIMX + d];
    }
    __syncthreads();

    // rmsnorm: F.normalize * sqrt(dh) * gamma ; q rows on warps 0-2, k rows on warps 4-6
    if (t < NTOK) {
        float ss = 0.f;
        #pragma unroll
        for (int d = 0; d < DIM_HEAD; d++) { float v = qs[t][d]; ss += v * v; }
        float sc = 5.656854249f / fmaxf(sqrtf(ss), 1e-12f);   // sqrt(32)
        #pragma unroll
        for (int d = 0; d < DIM_HEAD; d++) qs[t][d] *= sc * qg[d];
    } else if (t >= 128 && t < 128 + NTOK) {
        int r = t - 128;
        float ss = 0.f;
        #pragma unroll
        for (int d = 0; d < DIM_HEAD; d++) { float v = ks[r][d]; ss += v * v; }
        float sc = 5.656854249f / fmaxf(sqrtf(ss), 1e-12f);
        #pragma unroll
        for (int d = 0; d < DIM_HEAD; d++) ks[r][d] *= sc * kg[d];
    }
    __syncthreads();

    if (t < NTOK) {
        float qr[DIM_HEAD];
        #pragma unroll
        for (int d = 0; d < DIM_HEAD; d++) qr[d] = qs[t][d];

        float mx = -1e30f;
        for (int j = 0; j < NTOK; j++) {
            float s = 0.f;
            #pragma unroll
            for (int d = 0; d < DIM_HEAD; d++) s = fmaf(qr[d], ks[j][d], s);
            s += rel_emb[rel_idx[t * NTOK + j] * HEADS + h];
            ps[t][j] = s;
            mx = fmaxf(mx, s);
        }
        float sum = 0.f;
        for (int j = 0; j < NTOK; j++) {
            float p = __expf(ps[t][j] - mx);
            ps[t][j] = p;
            sum += p;
        }
        float inv = 1.f / sum;
        float accd[DIM_HEAD];
        #pragma unroll
        for (int d = 0; d < DIM_HEAD; d++) accd[d] = 0.f;
        for (int j = 0; j < NTOK; j++) {
            float p = ps[t][j] * inv;
            #pragma unroll
            for (int d = 0; d < DIM_HEAD; d++) accd[d] = fmaf(p, vs[j][d], accd[d]);
        }
        float* outp = g_o + (size_t)(b * NTOK + t) * DIMX + h * DIM_HEAD;
        #pragma unroll
        for (int d = 0; d < DIM_HEAD; d++) outp[d] = accd[d];
    }
}

// ---------------- launch ----------------
extern "C" void kernel_launch(void* const* d_in, const int* in_sizes, int n_in,
                              void* d_out, int out_size)
{
    const float* x       = (const float*)d_in[0];
    const float* cond    = (const float*)d_in[1];
    const float* fw1     = (const float*)d_in[2];
    const float* fb1     = (const float*)d_in[3];
    const float* fw2     = (const float*)d_in[4];
    const float* fb2     = (const float*)d_in[5];
    const float* wqkv    = (const float*)d_in[6];
    const float* qg      = (const float*)d_in[7];
    const float* kg      = (const float*)d_in[8];
    const float* rel_emb = (const float*)d_in[9];
    const float* wout    = (const float*)d_in[10];
    const int*   rel_idx = (const int*)d_in[11];
    float* out = (float*)d_out;

    float *p_xn, *p_qkv, *p_o;
    cudaGetSymbolAddress((void**)&p_xn,  g_xn);
    cudaGetSymbolAddress((void**)&p_qkv, g_qkv);
    cudaGetSymbolAddress((void**)&p_o,   g_o);

    // FiLM MLP
    film1_kernel<<<dim3(TWO_DIM / 256, B_IMG), 256>>>(cond, fw1, fb1);
    film2_kernel<<<dim3(TWO_DIM / 256, B_IMG), 256>>>(fw2, fb2);

    // LayerNorm + modulation
    ln_film_kernel<<<M_TOK, 256>>>(x);

    // qkv projection: (33280,1024) @ (1024,3072)
    sgemm_kernel<<<dim3((3 * DIMX) / BN, M_TOK / BM), 256>>>(p_xn, wqkv, p_qkv,
                                                             M_TOK, 3 * DIMX, DIMX);

    // attention per (b, h)
    attn_kernel<<<dim3(B_TOT, HEADS), 256>>>(qg, kg, rel_emb, rel_idx);

    // output projection: (33280,1024) @ (1024,1024)
    sgemm_kernel<<<dim3(DIMX / BN, M_TOK / BM), 256>>>(p_o, wout, out,
                                                       M_TOK, DIMX, DIMX);
}

// round 2
// speedup vs baseline: 1.7404x; 1.7404x over previous
#include <cuda_runtime.h>
#include <math.h>

// ---------------- problem constants ----------------
#define DIMX 1024
#define COND_DIM 512
#define HEADS 32
#define DIM_HEAD 32
#define NTOK 65              // ws*ws + 1 register token
#define B_TOT 512
#define B_IMG 16
#define M_TOK (B_TOT * NTOK) // 33280 = 260 * 128
#define TWO_DIM (2 * DIMX)

// ---------------- scratch (device globals; no runtime alloc allowed) ----------------
__device__ float g_h1[B_IMG * TWO_DIM];                   // FiLM hidden
__device__ float g_gb[B_IMG * TWO_DIM];                   // gamma|beta
__device__ float g_xn[(size_t)M_TOK * DIMX];              // modulated layernorm output
__device__ float g_qkv[(size_t)M_TOK * 3 * DIMX];         // qkv projection
__device__ float g_o[(size_t)M_TOK * DIMX];               // attention output (pre w_out)

// ---------------- FiLM MLP ----------------
__global__ __launch_bounds__(256) void film1_kernel(
    const float* __restrict__ cond, const float* __restrict__ w1,
    const float* __restrict__ b1)
{
    int j = blockIdx.x * 256 + threadIdx.x;   // 0..2047
    int i = blockIdx.y;                       // 0..15
    const float* c = cond + i * COND_DIM;
    float acc = b1[j];
    #pragma unroll 4
    for (int k = 0; k < COND_DIM; k++)
        acc = fmaf(c[k], w1[k * TWO_DIM + j], acc);
    g_h1[i * TWO_DIM + j] = acc / (1.f + __expf(-acc));
}

__global__ __launch_bounds__(256) void film2_kernel(
    const float* __restrict__ w2, const float* __restrict__ b2)
{
    int j = blockIdx.x * 256 + threadIdx.x;
    int i = blockIdx.y;
    const float* h = g_h1 + i * TWO_DIM;
    float acc = b2[j];
    #pragma unroll 4
    for (int k = 0; k < TWO_DIM; k++)
        acc = fmaf(h[k], w2[k * TWO_DIM + j], acc);
    g_gb[i * TWO_DIM + j] = acc;
}

// ---------------- LayerNorm + FiLM modulation ----------------
__global__ __launch_bounds__(256) void ln_film_kernel(const float* __restrict__ x)
{
    int row = blockIdx.x;                  // token row 0..33279
    int img = (row / NTOK) >> 5;           // b / 32  (d_rep = 512/16)
    const float4* xr = (const float4*)(x + (size_t)row * DIMX);
    int t = threadIdx.x;                   // 256 threads, 4 floats each
    float4 v = xr[t];
    float s  = v.x + v.y + v.z + v.w;
    float ss = v.x*v.x + v.y*v.y + v.z*v.z + v.w*v.w;

    __shared__ float red_s[8], red_ss[8];
    #pragma unroll
    for (int o = 16; o > 0; o >>= 1) {
        s  += __shfl_down_sync(0xffffffffu, s, o);
        ss += __shfl_down_sync(0xffffffffu, ss, o);
    }
    int warp = t >> 5, lane = t & 31;
    if (lane == 0) { red_s[warp] = s; red_ss[warp] = ss; }
    __syncthreads();
    if (warp == 0) {
        s  = (lane < 8) ? red_s[lane]  : 0.f;
        ss = (lane < 8) ? red_ss[lane] : 0.f;
        #pragma unroll
        for (int o = 4; o > 0; o >>= 1) {
            s  += __shfl_down_sync(0xffffffffu, s, o);
            ss += __shfl_down_sync(0xffffffffu, ss, o);
        }
        if (lane == 0) { red_s[0] = s; red_ss[0] = ss; }
    }
    __syncthreads();
    float mu  = red_s[0] * (1.f / DIMX);
    float var = red_ss[0] * (1.f / DIMX) - mu * mu;
    float rs  = rsqrtf(var + 1e-5f);

    const float4* gam = (const float4*)(g_gb + (size_t)img * TWO_DIM);
    const float4* bet = (const float4*)(g_gb + (size_t)img * TWO_DIM + DIMX);
    float4 gv = gam[t], bv = bet[t];
    float4 o;
    o.x = fmaf((v.x - mu) * rs, gv.x, bv.x);
    o.y = fmaf((v.y - mu) * rs, gv.y, bv.y);
    o.z = fmaf((v.z - mu) * rs, gv.z, bv.z);
    o.w = fmaf((v.w - mu) * rs, gv.w, bv.w);
    ((float4*)(g_xn + (size_t)row * DIMX))[t] = o;
}

// ---------------- TF32 tensor-core GEMM: C[M,N] = A[M,K] @ B[K,N] ----------------
// BM=BN=128, BK=16, 256 threads (8 warps), warp tile 64x32 via m16n8k8 tf32 mma.
// smem rows padded to stride 136 floats (136 mod 32 == 8) -> fragment LDS pattern
// bank = (8*(lane%4) + lane/4) mod 32 covers all 32 banks: conflict-free.
#define GBM 128
#define GBN 128
#define GBK 16
#define SSTRIDE 136

__device__ __forceinline__ float to_tf32(float x) {
    float r;
    asm("cvt.rna.tf32.f32 %0, %1;" : "=f"(r) : "f"(x));
    return r;
}

__device__ __forceinline__ void mma_tf32(float* d, const float* a, const float* b) {
    asm volatile(
        "mma.sync.aligned.m16n8k8.row.col.f32.tf32.tf32.f32 "
        "{%0,%1,%2,%3}, {%4,%5,%6,%7}, {%8,%9}, {%0,%1,%2,%3};\n"
        : "+f"(d[0]), "+f"(d[1]), "+f"(d[2]), "+f"(d[3])
        : "r"(__float_as_uint(a[0])), "r"(__float_as_uint(a[1])),
          "r"(__float_as_uint(a[2])), "r"(__float_as_uint(a[3])),
          "r"(__float_as_uint(b[0])), "r"(__float_as_uint(b[1])));
}

__global__ __launch_bounds__(256) void tf32_gemm_kernel(
    const float* __restrict__ A, const float* __restrict__ B,
    float* __restrict__ C, int M, int N, int K)
{
    __shared__ float sA[2][GBK * SSTRIDE];   // sA[k][m]
    __shared__ float sB[2][GBK * SSTRIDE];   // sB[k][n]

    const int tid   = threadIdx.x;
    const int warp  = tid >> 5;
    const int lane  = tid & 31;
    const int group = lane >> 2;     // 0..7
    const int tig   = lane & 3;      // 0..3
    const int wm = (warp >> 2) * 64; // warp row offset (0 or 64)
    const int wn = (warp & 3) * 32;  // warp col offset (0..96)

    const int row0 = blockIdx.y * GBM;
    const int col0 = blockIdx.x * GBN;

    // A loader mapping: row = tid&127, k-chunk = (tid>>7)*8 (two float4 along K)
    const int a_row = tid & 127;
    const int a_kc  = (tid >> 7) * 8;
    const float* Aptr = A + (size_t)(row0 + a_row) * K + a_kc;
    // B loader mapping: k-row = tid>>4 (0..15), n-chunk = (tid&15)*4 (two float4, +0/+64)
    const int b_kr = tid >> 4;
    const int b_nc = (tid & 15) * 4;
    const float* Bptr = B + (size_t)b_kr * N + col0 + b_nc;

    float acc[4][4][4];
    #pragma unroll
    for (int mi = 0; mi < 4; mi++)
        #pragma unroll
        for (int nj = 0; nj < 4; nj++)
            #pragma unroll
            for (int c = 0; c < 4; c++) acc[mi][nj][c] = 0.f;

    // ---- prologue: load tile 0 ----
    {
        float4 a0 = *(const float4*)(Aptr);
        float4 a1 = *(const float4*)(Aptr + 4);
        sA[0][(a_kc + 0) * SSTRIDE + a_row] = to_tf32(a0.x);
        sA[0][(a_kc + 1) * SSTRIDE + a_row] = to_tf32(a0.y);
        sA[0][(a_kc + 2) * SSTRIDE + a_row] = to_tf32(a0.z);
        sA[0][(a_kc + 3) * SSTRIDE + a_row] = to_tf32(a0.w);
        sA[0][(a_kc + 4) * SSTRIDE + a_row] = to_tf32(a1.x);
        sA[0][(a_kc + 5) * SSTRIDE + a_row] = to_tf32(a1.y);
        sA[0][(a_kc + 6) * SSTRIDE + a_row] = to_tf32(a1.z);
        sA[0][(a_kc + 7) * SSTRIDE + a_row] = to_tf32(a1.w);
        float4 b0 = *(const float4*)(Bptr);
        float4 b1 = *(const float4*)(Bptr + 64);
        float4 w0 = make_float4(to_tf32(b0.x), to_tf32(b0.y), to_tf32(b0.z), to_tf32(b0.w));
        float4 w1 = make_float4(to_tf32(b1.x), to_tf32(b1.y), to_tf32(b1.z), to_tf32(b1.w));
        *(float4*)&sB[0][b_kr * SSTRIDE + b_nc]      = w0;
        *(float4*)&sB[0][b_kr * SSTRIDE + b_nc + 64] = w1;
    }
    __syncthreads();

    const int kiters = K / GBK;
    for (int kt = 0; kt < kiters; kt++) {
        const int buf = kt & 1;
        float4 a0, a1, b0, b1;
        const bool has_next = (kt + 1 < kiters);
        if (has_next) {
            int k0 = (kt + 1) * GBK;
            a0 = *(const float4*)(Aptr + k0);
            a1 = *(const float4*)(Aptr + k0 + 4);
            b0 = *(const float4*)(Bptr + (size_t)k0 * N);
            b1 = *(const float4*)(Bptr + (size_t)k0 * N + 64);
        }

        // ---- compute 2 k-steps from buf ----
        #pragma unroll
        for (int ks = 0; ks < GBK; ks += 8) {
            float af[4][4];
            #pragma unroll
            for (int mi = 0; mi < 4; mi++) {
                int m = wm + mi * 16 + group;
                af[mi][0] = sA[buf][(ks + tig) * SSTRIDE + m];
                af[mi][1] = sA[buf][(ks + tig) * SSTRIDE + m + 8];
                af[mi][2] = sA[buf][(ks + tig + 4) * SSTRIDE + m];
                af[mi][3] = sA[buf][(ks + tig + 4) * SSTRIDE + m + 8];
            }
            float bf[4][2];
            #pragma unroll
            for (int nj = 0; nj < 4; nj++) {
                int n = wn + nj * 8 + group;
                bf[nj][0] = sB[buf][(ks + tig) * SSTRIDE + n];
                bf[nj][1] = sB[buf][(ks + tig + 4) * SSTRIDE + n];
            }
            #pragma unroll
            for (int mi = 0; mi < 4; mi++)
                #pragma unroll
                for (int nj = 0; nj < 4; nj++)
                    mma_tf32(acc[mi][nj], af[mi], bf[nj]);
        }

        if (has_next) {
            const int nbuf = buf ^ 1;
            __syncthreads();
            sA[nbuf][(a_kc + 0) * SSTRIDE + a_row] = to_tf32(a0.x);
            sA[nbuf][(a_kc + 1) * SSTRIDE + a_row] = to_tf32(a0.y);
            sA[nbuf][(a_kc + 2) * SSTRIDE + a_row] = to_tf32(a0.z);
            sA[nbuf][(a_kc + 3) * SSTRIDE + a_row] = to_tf32(a0.w);
            sA[nbuf][(a_kc + 4) * SSTRIDE + a_row] = to_tf32(a1.x);
            sA[nbuf][(a_kc + 5) * SSTRIDE + a_row] = to_tf32(a1.y);
            sA[nbuf][(a_kc + 6) * SSTRIDE + a_row] = to_tf32(a1.z);
            sA[nbuf][(a_kc + 7) * SSTRIDE + a_row] = to_tf32(a1.w);
            float4 w0 = make_float4(to_tf32(b0.x), to_tf32(b0.y), to_tf32(b0.z), to_tf32(b0.w));
            float4 w1 = make_float4(to_tf32(b1.x), to_tf32(b1.y), to_tf32(b1.z), to_tf32(b1.w));
            *(float4*)&sB[nbuf][b_kr * SSTRIDE + b_nc]      = w0;
            *(float4*)&sB[nbuf][b_kr * SSTRIDE + b_nc + 64] = w1;
            __syncthreads();
        }
    }

    // ---- epilogue: c0/c1 at (row, 2*tig), c2/c3 at (row+8, 2*tig) ----
    #pragma unroll
    for (int mi = 0; mi < 4; mi++) {
        #pragma unroll
        for (int nj = 0; nj < 4; nj++) {
            int r = row0 + wm + mi * 16 + group;
            int c = col0 + wn + nj * 8 + tig * 2;
            *(float2*)(C + (size_t)r * N + c)       = make_float2(acc[mi][nj][0], acc[mi][nj][1]);
            *(float2*)(C + (size_t)(r + 8) * N + c) = make_float2(acc[mi][nj][2], acc[mi][nj][3]);
        }
    }
}

// ---------------- per-(b,h) attention: rmsnorm(q,k) -> sim+bias -> softmax -> PV ----------------
__global__ __launch_bounds__(256) void attn_kernel(
    const float* __restrict__ q_gamma, const float* __restrict__ k_gamma,
    const float* __restrict__ rel_emb, const int* __restrict__ rel_idx)
{
    int b = blockIdx.x;      // 0..511
    int h = blockIdx.y;      // 0..31

    __shared__ float qs[NTOK][DIM_HEAD];
    __shared__ float ks[NTOK][DIM_HEAD];
    __shared__ float vs[NTOK][DIM_HEAD];
    __shared__ float ps[NTOK][NTOK];
    __shared__ float qg[DIM_HEAD], kg[DIM_HEAD];

    int t = threadIdx.x;     // 256
    if (t < DIM_HEAD) {
        qg[t] = q_gamma[h * DIM_HEAD + t];
        kg[t] = k_gamma[h * DIM_HEAD + t];
    }
    const float* base = g_qkv + (size_t)(b * NTOK) * (3 * DIMX) + h * DIM_HEAD;
    for (int idx = t; idx < NTOK * DIM_HEAD; idx += 256) {
        int n = idx >> 5, d = idx & 31;
        const float* r = base + (size_t)n * (3 * DIMX);
        qs[n][d] = r[d];
        ks[n][d] = r[DIMX + d];
        vs[n][d] = r[2 * DIMX + d];
    }
    __syncthreads();

    if (t < NTOK) {
        float ss = 0.f;
        #pragma unroll
        for (int d = 0; d < DIM_HEAD; d++) { float v = qs[t][d]; ss += v * v; }
        float sc = 5.656854249f / fmaxf(sqrtf(ss), 1e-12f);   // sqrt(32)
        #pragma unroll
        for (int d = 0; d < DIM_HEAD; d++) qs[t][d] *= sc * qg[d];
    } else if (t >= 128 && t < 128 + NTOK) {
        int r = t - 128;
        float ss = 0.f;
        #pragma unroll
        for (int d = 0; d < DIM_HEAD; d++) { float v = ks[r][d]; ss += v * v; }
        float sc = 5.656854249f / fmaxf(sqrtf(ss), 1e-12f);
        #pragma unroll
        for (int d = 0; d < DIM_HEAD; d++) ks[r][d] *= sc * kg[d];
    }
    __syncthreads();

    if (t < NTOK) {
        float qr[DIM_HEAD];
        #pragma unroll
        for (int d = 0; d < DIM_HEAD; d++) qr[d] = qs[t][d];

        float mx = -1e30f;
        for (int j = 0; j < NTOK; j++) {
            float s = 0.f;
            #pragma unroll
            for (int d = 0; d < DIM_HEAD; d++) s = fmaf(qr[d], ks[j][d], s);
            s += rel_emb[rel_idx[t * NTOK + j] * HEADS + h];
            ps[t][j] = s;
            mx = fmaxf(mx, s);
        }
        float sum = 0.f;
        for (int j = 0; j < NTOK; j++) {
            float p = __expf(ps[t][j] - mx);
            ps[t][j] = p;
            sum += p;
        }
        float inv = 1.f / sum;
        float accd[DIM_HEAD];
        #pragma unroll
        for (int d = 0; d < DIM_HEAD; d++) accd[d] = 0.f;
        for (int j = 0; j < NTOK; j++) {
            float p = ps[t][j] * inv;
            #pragma unroll
            for (int d = 0; d < DIM_HEAD; d++) accd[d] = fmaf(p, vs[j][d], accd[d]);
        }
        float* outp = g_o + (size_t)(b * NTOK + t) * DIMX + h * DIM_HEAD;
        #pragma unroll
        for (int d = 0; d < DIM_HEAD; d++) outp[d] = accd[d];
    }
}

// ---------------- launch ----------------
extern "C" void kernel_launch(void* const* d_in, const int* in_sizes, int n_in,
                              void* d_out, int out_size)
{
    const float* x       = (const float*)d_in[0];
    const float* cond    = (const float*)d_in[1];
    const float* fw1     = (const float*)d_in[2];
    const float* fb1     = (const float*)d_in[3];
    const float* fw2     = (const float*)d_in[4];
    const float* fb2     = (const float*)d_in[5];
    const float* wqkv    = (const float*)d_in[6];
    const float* qg      = (const float*)d_in[7];
    const float* kg      = (const float*)d_in[8];
    const float* rel_emb = (const float*)d_in[9];
    const float* wout    = (const float*)d_in[10];
    const int*   rel_idx = (const int*)d_in[11];
    float* out = (float*)d_out;

    float *p_xn, *p_qkv, *p_o;
    cudaGetSymbolAddress((void**)&p_xn,  g_xn);
    cudaGetSymbolAddress((void**)&p_qkv, g_qkv);
    cudaGetSymbolAddress((void**)&p_o,   g_o);

    // FiLM MLP
    film1_kernel<<<dim3(TWO_DIM / 256, B_IMG), 256>>>(cond, fw1, fb1);
    film2_kernel<<<dim3(TWO_DIM / 256, B_IMG), 256>>>(fw2, fb2);

    // LayerNorm + modulation
    ln_film_kernel<<<M_TOK, 256>>>(x);

    // qkv projection: (33280,1024) @ (1024,3072) on tf32 tensor cores
    tf32_gemm_kernel<<<dim3((3 * DIMX) / GBN, M_TOK / GBM), 256>>>(p_xn, wqkv, p_qkv,
                                                                   M_TOK, 3 * DIMX, DIMX);

    // attention per (b, h)
    attn_kernel<<<dim3(B_TOT, HEADS), 256>>>(qg, kg, rel_emb, rel_idx);

    // output projection: (33280,1024) @ (1024,1024) on tf32 tensor cores
    tf32_gemm_kernel<<<dim3(DIMX / GBN, M_TOK / GBM), 256>>>(p_o, wout, out,
                                                             M_TOK, DIMX, DIMX);
}

// round 3
// speedup vs baseline: 1.7473x; 1.0040x over previous
#include <cuda_runtime.h>
#include <math.h>

// ---------------- problem constants ----------------
#define DIMX 1024
#define COND_DIM 512
#define HEADS 32
#define DIM_HEAD 32
#define NTOK 65              // ws*ws + 1 register token
#define B_TOT 512
#define B_IMG 16
#define M_TOK (B_TOT * NTOK) // 33280 = 260 * 128
#define TWO_DIM (2 * DIMX)

// ---------------- scratch (device globals; no runtime alloc allowed) ----------------
__device__ float g_h1[B_IMG * TWO_DIM];                   // FiLM hidden
__device__ float g_gb[B_IMG * TWO_DIM];                   // gamma|beta
__device__ float g_xn[(size_t)M_TOK * DIMX];              // modulated layernorm output
__device__ float g_qkv[(size_t)M_TOK * 3 * DIMX];         // qkv projection
__device__ float g_o[(size_t)M_TOK * DIMX];               // attention output (pre w_out)

// ---------------- FiLM MLP ----------------
__global__ __launch_bounds__(256) void film1_kernel(
    const float* __restrict__ cond, const float* __restrict__ w1,
    const float* __restrict__ b1)
{
    int j = blockIdx.x * 256 + threadIdx.x;   // 0..2047
    int i = blockIdx.y;                       // 0..15
    const float* c = cond + i * COND_DIM;
    float acc = b1[j];
    #pragma unroll 4
    for (int k = 0; k < COND_DIM; k++)
        acc = fmaf(c[k], w1[k * TWO_DIM + j], acc);
    g_h1[i * TWO_DIM + j] = acc / (1.f + __expf(-acc));
}

__global__ __launch_bounds__(256) void film2_kernel(
    const float* __restrict__ w2, const float* __restrict__ b2)
{
    int j = blockIdx.x * 256 + threadIdx.x;
    int i = blockIdx.y;
    const float* h = g_h1 + i * TWO_DIM;
    float acc = b2[j];
    #pragma unroll 4
    for (int k = 0; k < TWO_DIM; k++)
        acc = fmaf(h[k], w2[k * TWO_DIM + j], acc);
    g_gb[i * TWO_DIM + j] = acc;
}

// ---------------- LayerNorm + FiLM modulation ----------------
__global__ __launch_bounds__(256) void ln_film_kernel(const float* __restrict__ x)
{
    int row = blockIdx.x;                  // token row 0..33279
    int img = (row / NTOK) >> 5;           // b / 32  (d_rep = 512/16)
    const float4* xr = (const float4*)(x + (size_t)row * DIMX);
    int t = threadIdx.x;                   // 256 threads, 4 floats each
    float4 v = xr[t];
    float s  = v.x + v.y + v.z + v.w;
    float ss = v.x*v.x + v.y*v.y + v.z*v.z + v.w*v.w;

    __shared__ float red_s[8], red_ss[8];
    #pragma unroll
    for (int o = 16; o > 0; o >>= 1) {
        s  += __shfl_down_sync(0xffffffffu, s, o);
        ss += __shfl_down_sync(0xffffffffu, ss, o);
    }
    int warp = t >> 5, lane = t & 31;
    if (lane == 0) { red_s[warp] = s; red_ss[warp] = ss; }
    __syncthreads();
    if (warp == 0) {
        s  = (lane < 8) ? red_s[lane]  : 0.f;
        ss = (lane < 8) ? red_ss[lane] : 0.f;
        #pragma unroll
        for (int o = 4; o > 0; o >>= 1) {
            s  += __shfl_down_sync(0xffffffffu, s, o);
            ss += __shfl_down_sync(0xffffffffu, ss, o);
        }
        if (lane == 0) { red_s[0] = s; red_ss[0] = ss; }
    }
    __syncthreads();
    float mu  = red_s[0] * (1.f / DIMX);
    float var = red_ss[0] * (1.f / DIMX) - mu * mu;
    float rs  = rsqrtf(var + 1e-5f);

    const float4* gam = (const float4*)(g_gb + (size_t)img * TWO_DIM);
    const float4* bet = (const float4*)(g_gb + (size_t)img * TWO_DIM + DIMX);
    float4 gv = gam[t], bv = bet[t];
    float4 o;
    o.x = fmaf((v.x - mu) * rs, gv.x, bv.x);
    o.y = fmaf((v.y - mu) * rs, gv.y, bv.y);
    o.z = fmaf((v.z - mu) * rs, gv.z, bv.z);
    o.w = fmaf((v.w - mu) * rs, gv.w, bv.w);
    ((float4*)(g_xn + (size_t)row * DIMX))[t] = o;
}

// ---------------- TF32 tensor-core GEMM: C[M,N] = A[M,K] @ B[K,N] ----------------
// BM=BN=128, BK=16, 256 threads (8 warps), warp tile 64x32 via m16n8k8 tf32 mma.
// smem rows padded to stride 136 floats (136 mod 32 == 8) -> fragment LDS pattern
// bank = (8*(lane%4) + lane/4) mod 32 covers all 32 banks: conflict-free.
#define GBM 128
#define GBN 128
#define GBK 16
#define SSTRIDE 136

__device__ __forceinline__ float to_tf32(float x) {
    float r;
    asm("cvt.rna.tf32.f32 %0, %1;" : "=f"(r) : "f"(x));
    return r;
}

__device__ __forceinline__ void mma_tf32(float* d, const float* a, const float* b) {
    asm volatile(
        "mma.sync.aligned.m16n8k8.row.col.f32.tf32.tf32.f32 "
        "{%0,%1,%2,%3}, {%4,%5,%6,%7}, {%8,%9}, {%0,%1,%2,%3};\n"
        : "+f"(d[0]), "+f"(d[1]), "+f"(d[2]), "+f"(d[3])
        : "r"(__float_as_uint(a[0])), "r"(__float_as_uint(a[1])),
          "r"(__float_as_uint(a[2])), "r"(__float_as_uint(a[3])),
          "r"(__float_as_uint(b[0])), "r"(__float_as_uint(b[1])));
}

__global__ __launch_bounds__(256) void tf32_gemm_kernel(
    const float* __restrict__ A, const float* __restrict__ B,
    float* __restrict__ C, int M, int N, int K)
{
    __shared__ float sA[2][GBK * SSTRIDE];   // sA[k][m]
    __shared__ float sB[2][GBK * SSTRIDE];   // sB[k][n]

    const int tid   = threadIdx.x;
    const int warp  = tid >> 5;
    const int lane  = tid & 31;
    const int group = lane >> 2;     // 0..7
    const int tig   = lane & 3;      // 0..3
    const int wm = (warp >> 2) * 64; // warp row offset (0 or 64)
    const int wn = (warp & 3) * 32;  // warp col offset (0..96)

    const int row0 = blockIdx.y * GBM;
    const int col0 = blockIdx.x * GBN;

    // A loader mapping: row = tid&127, k-chunk = (tid>>7)*8 (two float4 along K)
    const int a_row = tid & 127;
    const int a_kc  = (tid >> 7) * 8;
    const float* Aptr = A + (size_t)(row0 + a_row) * K + a_kc;
    // B loader mapping: k-row = tid>>4 (0..15), n-chunk = (tid&15)*4 (two float4, +0/+64)
    const int b_kr = tid >> 4;
    const int b_nc = (tid & 15) * 4;
    const float* Bptr = B + (size_t)b_kr * N + col0 + b_nc;

    float acc[4][4][4];
    #pragma unroll
    for (int mi = 0; mi < 4; mi++)
        #pragma unroll
        for (int nj = 0; nj < 4; nj++)
            #pragma unroll
            for (int c = 0; c < 4; c++) acc[mi][nj][c] = 0.f;

    // ---- prologue: load tile 0 ----
    {
        float4 a0 = *(const float4*)(Aptr);
        float4 a1 = *(const float4*)(Aptr + 4);
        sA[0][(a_kc + 0) * SSTRIDE + a_row] = to_tf32(a0.x);
        sA[0][(a_kc + 1) * SSTRIDE + a_row] = to_tf32(a0.y);
        sA[0][(a_kc + 2) * SSTRIDE + a_row] = to_tf32(a0.z);
        sA[0][(a_kc + 3) * SSTRIDE + a_row] = to_tf32(a0.w);
        sA[0][(a_kc + 4) * SSTRIDE + a_row] = to_tf32(a1.x);
        sA[0][(a_kc + 5) * SSTRIDE + a_row] = to_tf32(a1.y);
        sA[0][(a_kc + 6) * SSTRIDE + a_row] = to_tf32(a1.z);
        sA[0][(a_kc + 7) * SSTRIDE + a_row] = to_tf32(a1.w);
        float4 b0 = *(const float4*)(Bptr);
        float4 b1 = *(const float4*)(Bptr + 64);
        float4 w0 = make_float4(to_tf32(b0.x), to_tf32(b0.y), to_tf32(b0.z), to_tf32(b0.w));
        float4 w1 = make_float4(to_tf32(b1.x), to_tf32(b1.y), to_tf32(b1.z), to_tf32(b1.w));
        *(float4*)&sB[0][b_kr * SSTRIDE + b_nc]      = w0;
        *(float4*)&sB[0][b_kr * SSTRIDE + b_nc + 64] = w1;
    }
    __syncthreads();

    const int kiters = K / GBK;
    for (int kt = 0; kt < kiters; kt++) {
        const int buf = kt & 1;
        float4 a0, a1, b0, b1;
        const bool has_next = (kt + 1 < kiters);
        if (has_next) {
            int k0 = (kt + 1) * GBK;
            a0 = *(const float4*)(Aptr + k0);
            a1 = *(const float4*)(Aptr + k0 + 4);
            b0 = *(const float4*)(Bptr + (size_t)k0 * N);
            b1 = *(const float4*)(Bptr + (size_t)k0 * N + 64);
        }

        // ---- compute 2 k-steps from buf ----
        #pragma unroll
        for (int ks = 0; ks < GBK; ks += 8) {
            float af[4][4];
            #pragma unroll
            for (int mi = 0; mi < 4; mi++) {
                int m = wm + mi * 16 + group;
                af[mi][0] = sA[buf][(ks + tig) * SSTRIDE + m];
                af[mi][1] = sA[buf][(ks + tig) * SSTRIDE + m + 8];
                af[mi][2] = sA[buf][(ks + tig + 4) * SSTRIDE + m];
                af[mi][3] = sA[buf][(ks + tig + 4) * SSTRIDE + m + 8];
            }
            float bf[4][2];
            #pragma unroll
            for (int nj = 0; nj < 4; nj++) {
                int n = wn + nj * 8 + group;
                bf[nj][0] = sB[buf][(ks + tig) * SSTRIDE + n];
                bf[nj][1] = sB[buf][(ks + tig + 4) * SSTRIDE + n];
            }
            #pragma unroll
            for (int mi = 0; mi < 4; mi++)
                #pragma unroll
                for (int nj = 0; nj < 4; nj++)
                    mma_tf32(acc[mi][nj], af[mi], bf[nj]);
        }

        if (has_next) {
            const int nbuf = buf ^ 1;
            __syncthreads();
            sA[nbuf][(a_kc + 0) * SSTRIDE + a_row] = to_tf32(a0.x);
            sA[nbuf][(a_kc + 1) * SSTRIDE + a_row] = to_tf32(a0.y);
            sA[nbuf][(a_kc + 2) * SSTRIDE + a_row] = to_tf32(a0.z);
            sA[nbuf][(a_kc + 3) * SSTRIDE + a_row] = to_tf32(a0.w);
            sA[nbuf][(a_kc + 4) * SSTRIDE + a_row] = to_tf32(a1.x);
            sA[nbuf][(a_kc + 5) * SSTRIDE + a_row] = to_tf32(a1.y);
            sA[nbuf][(a_kc + 6) * SSTRIDE + a_row] = to_tf32(a1.z);
            sA[nbuf][(a_kc + 7) * SSTRIDE + a_row] = to_tf32(a1.w);
            float4 w0 = make_float4(to_tf32(b0.x), to_tf32(b0.y), to_tf32(b0.z), to_tf32(b0.w));
            float4 w1 = make_float4(to_tf32(b1.x), to_tf32(b1.y), to_tf32(b1.z), to_tf32(b1.w));
            *(float4*)&sB[nbuf][b_kr * SSTRIDE + b_nc]      = w0;
            *(float4*)&sB[nbuf][b_kr * SSTRIDE + b_nc + 64] = w1;
            __syncthreads();
        }
    }

    // ---- epilogue: c0/c1 at (row, 2*tig), c2/c3 at (row+8, 2*tig) ----
    #pragma unroll
    for (int mi = 0; mi < 4; mi++) {
        #pragma unroll
        for (int nj = 0; nj < 4; nj++) {
            int r = row0 + wm + mi * 16 + group;
            int c = col0 + wn + nj * 8 + tig * 2;
            *(float2*)(C + (size_t)r * N + c)       = make_float2(acc[mi][nj][0], acc[mi][nj][1]);
            *(float2*)(C + (size_t)(r + 8) * N + c) = make_float2(acc[mi][nj][2], acc[mi][nj][3]);
        }
    }
}

// ---------------- per-(b,h) attention: rmsnorm(q,k) -> sim+bias -> softmax -> PV ----------------
__global__ __launch_bounds__(256) void attn_kernel(
    const float* __restrict__ q_gamma, const float* __restrict__ k_gamma,
    const float* __restrict__ rel_emb, const int* __restrict__ rel_idx)
{
    int b = blockIdx.x;      // 0..511
    int h = blockIdx.y;      // 0..31

    __shared__ float qs[NTOK][DIM_HEAD];
    __shared__ float ks[NTOK][DIM_HEAD];
    __shared__ float vs[NTOK][DIM_HEAD];
    __shared__ float ps[NTOK][NTOK];
    __shared__ float qg[DIM_HEAD], kg[DIM_HEAD];

    int t = threadIdx.x;     // 256
    if (t < DIM_HEAD) {
        qg[t] = q_gamma[h * DIM_HEAD + t];
        kg[t] = k_gamma[h * DIM_HEAD + t];
    }
    const float* base = g_qkv + (size_t)(b * NTOK) * (3 * DIMX) + h * DIM_HEAD;
    for (int idx = t; idx < NTOK * DIM_HEAD; idx += 256) {
        int n = idx >> 5, d = idx & 31;
        const float* r = base + (size_t)n * (3 * DIMX);
        qs[n][d] = r[d];
        ks[n][d] = r[DIMX + d];
        vs[n][d] = r[2 * DIMX + d];
    }
    __syncthreads();

    if (t < NTOK) {
        float ss = 0.f;
        #pragma unroll
        for (int d = 0; d < DIM_HEAD; d++) { float v = qs[t][d]; ss += v * v; }
        float sc = 5.656854249f / fmaxf(sqrtf(ss), 1e-12f);   // sqrt(32)
        #pragma unroll
        for (int d = 0; d < DIM_HEAD; d++) qs[t][d] *= sc * qg[d];
    } else if (t >= 128 && t < 128 + NTOK) {
        int r = t - 128;
        float ss = 0.f;
        #pragma unroll
        for (int d = 0; d < DIM_HEAD; d++) { float v = ks[r][d]; ss += v * v; }
        float sc = 5.656854249f / fmaxf(sqrtf(ss), 1e-12f);
        #pragma unroll
        for (int d = 0; d < DIM_HEAD; d++) ks[r][d] *= sc * kg[d];
    }
    __syncthreads();

    if (t < NTOK) {
        float qr[DIM_HEAD];
        #pragma unroll
        for (int d = 0; d < DIM_HEAD; d++) qr[d] = qs[t][d];

        float mx = -1e30f;
        for (int j = 0; j < NTOK; j++) {
            float s = 0.f;
            #pragma unroll
            for (int d = 0; d < DIM_HEAD; d++) s = fmaf(qr[d], ks[j][d], s);
            s += rel_emb[rel_idx[t * NTOK + j] * HEADS + h];
            ps[t][j] = s;
            mx = fmaxf(mx, s);
        }
        float sum = 0.f;
        for (int j = 0; j < NTOK; j++) {
            float p = __expf(ps[t][j] - mx);
            ps[t][j] = p;
            sum += p;
        }
        float inv = 1.f / sum;
        float accd[DIM_HEAD];
        #pragma unroll
        for (int d = 0; d < DIM_HEAD; d++) accd[d] = 0.f;
        for (int j = 0; j < NTOK; j++) {
            float p = ps[t][j] * inv;
            #pragma unroll
            for (int d = 0; d < DIM_HEAD; d++) accd[d] = fmaf(p, vs[j][d], accd[d]);
        }
        float* outp = g_o + (size_t)(b * NTOK + t) * DIMX + h * DIM_HEAD;
        #pragma unroll
        for (int d = 0; d < DIM_HEAD; d++) outp[d] = accd[d];
    }
}

// ---------------- launch ----------------
extern "C" void kernel_launch(void* const* d_in, const int* in_sizes, int n_in,
                              void* d_out, int out_size)
{
    const float* x       = (const float*)d_in[0];
    const float* cond    = (const float*)d_in[1];
    const float* fw1     = (const float*)d_in[2];
    const float* fb1     = (const float*)d_in[3];
    const float* fw2     = (const float*)d_in[4];
    const float* fb2     = (const float*)d_in[5];
    const float* wqkv    = (const float*)d_in[6];
    const float* qg      = (const float*)d_in[7];
    const float* kg      = (const float*)d_in[8];
    const float* rel_emb = (const float*)d_in[9];
    const float* wout    = (const float*)d_in[10];
    const int*   rel_idx = (const int*)d_in[11];
    float* out = (float*)d_out;

    float *p_xn, *p_qkv, *p_o;
    cudaGetSymbolAddress((void**)&p_xn,  g_xn);
    cudaGetSymbolAddress((void**)&p_qkv, g_qkv);
    cudaGetSymbolAddress((void**)&p_o,   g_o);

    // FiLM MLP
    film1_kernel<<<dim3(TWO_DIM / 256, B_IMG), 256>>>(cond, fw1, fb1);
    film2_kernel<<<dim3(TWO_DIM / 256, B_IMG), 256>>>(fw2, fb2);

    // LayerNorm + modulation
    ln_film_kernel<<<M_TOK, 256>>>(x);

    // qkv projection: (33280,1024) @ (1024,3072) on tf32 tensor cores
    tf32_gemm_kernel<<<dim3((3 * DIMX) / GBN, M_TOK / GBM), 256>>>(p_xn, wqkv, p_qkv,
                                                                   M_TOK, 3 * DIMX, DIMX);

    // attention per (b, h)
    attn_kernel<<<dim3(B_TOT, HEADS), 256>>>(qg, kg, rel_emb, rel_idx);

    // output projection: (33280,1024) @ (1024,1024) on tf32 tensor cores
    tf32_gemm_kernel<<<dim3(DIMX / GBN, M_TOK / GBM), 256>>>(p_o, wout, out,
                                                             M_TOK, DIMX, DIMX);
}

// round 5
// speedup vs baseline: 1.7703x; 1.0132x over previous
#include <cuda_runtime.h>
#include <cuda_fp16.h>
#include <math.h>
#include <stdint.h>

#define DIMX 1024
#define COND_DIM 512
#define HEADS 32
#define DIM_HEAD 32
#define NTOK 65
#define B_TOT 512
#define B_IMG 16
#define M_TOK (B_TOT * NTOK)
#define TWO_DIM (2 * DIMX)

__device__ float  g_h1[B_IMG * TWO_DIM];
__device__ float  g_gb[B_IMG * TWO_DIM];
__device__ __half g_xnh[(size_t)M_TOK * DIMX];            // half LN output
__device__ float  g_qkv[(size_t)M_TOK * 3 * DIMX];        // qkv (fp32)
__device__ __half g_oh[(size_t)M_TOK * DIMX];             // half attn output
__device__ __half g_wqkvT[(size_t)3 * DIMX * DIMX];       // [3072][1024] k-major half
__device__ __half g_woutT[(size_t)DIMX * DIMX];           // [1024][1024] k-major half

#define CPA16(d, s) asm volatile("cp.async.cg.shared.global [%0], [%1], 16;" :: "r"(d), "l"(s) : "memory")
#define CPC()   asm volatile("cp.async.commit_group;" ::: "memory")
#define CPW0()  asm volatile("cp.async.wait_group 0;" ::: "memory")

__device__ __forceinline__ uint32_t smem_u32(const void* p) {
    uint32_t a; asm("{ .reg .u64 t; cvta.to.shared.u64 t, %1; cvt.u32.u64 %0, t; }" : "=r"(a) : "l"(p));
    return a;
}
__device__ __forceinline__ void mma_f16(float* d, const uint32_t* a, const uint32_t* b) {
    asm volatile(
        "mma.sync.aligned.m16n8k16.row.col.f32.f16.f16.f32 "
        "{%0,%1,%2,%3}, {%4,%5,%6,%7}, {%8,%9}, {%0,%1,%2,%3};\n"
        : "+f"(d[0]), "+f"(d[1]), "+f"(d[2]), "+f"(d[3])
        : "r"(a[0]), "r"(a[1]), "r"(a[2]), "r"(a[3]), "r"(b[0]), "r"(b[1]));
}

// ---- weight transpose + fp16 convert: W[K][N] f32 -> WT[N][K] half ----
__global__ __launch_bounds__(256) void wtrans_kernel(
    const float* __restrict__ W, __half* __restrict__ WT, int K, int N)
{
    __shared__ float t[32][33];
    int tx = threadIdx.x & 31, ty = threadIdx.x >> 5;   // 32 x 8
    int n0 = blockIdx.x * 32, k0 = blockIdx.y * 32;
    #pragma unroll
    for (int r = 0; r < 32; r += 8)
        t[ty + r][tx] = W[(size_t)(k0 + ty + r) * N + n0 + tx];
    __syncthreads();
    #pragma unroll
    for (int r = 0; r < 32; r += 8)
        WT[(size_t)(n0 + ty + r) * K + k0 + tx] = __float2half_rn(t[tx][ty + r]);
}

// ---- fp16 tensor-core GEMM: C[M,N](f32) = Ah[M,K] @ BtT[N,K]^T ----
// tile 128x256x32, 8 warps, warp tile 64x64, cp.async 2-stage.
#define ASTR 40                         // halves per smem row (32 + 8 pad)
#define A_BYTES (128 * ASTR * 2)        // 10240
#define B_BYTES (256 * ASTR * 2)        // 20480
#define STG_B (A_BYTES + B_BYTES)       // 30720
#define HG_SMEM (2 * STG_B)

__global__ __launch_bounds__(256) void hgemm_kernel(
    const __half* __restrict__ A, const __half* __restrict__ Bt,
    float* __restrict__ C, int N, int K)
{
    extern __shared__ char sm[];
    const uint32_t sb = smem_u32(sm);
    const int tid = threadIdx.x, warp = tid >> 5, lane = tid & 31;
    const int g = lane >> 2, tig = lane & 3;
    const int wm = (warp & 1) * 64, wn = (warp >> 1) * 64;
    const int row0 = blockIdx.y * 128, col0 = blockIdx.x * 256;

    float acc[4][8][4];
    #pragma unroll
    for (int mi = 0; mi < 4; mi++)
        #pragma unroll
        for (int nj = 0; nj < 8; nj++)
            #pragma unroll
            for (int c = 0; c < 4; c++) acc[mi][nj][c] = 0.f;

    // chunk mappings (16B chunks)
    const int a_row = tid >> 1, a_kc = tid & 1;          // A: 512 chunks, 2/thread (kc 0..3 via +2)
    const int b_row = tid >> 2, b_kc = tid & 3;          // B: 1024 chunks, 4/thread (row +64 step)

    const int KITERS = K >> 5;
    // prologue: stage 0
    {
        #pragma unroll
        for (int p = 0; p < 2; p++) {
            int kc = a_kc + p * 2;
            CPA16(sb + a_row * 80 + kc * 16, A + (size_t)(row0 + a_row) * K + kc * 8);
        }
        #pragma unroll
        for (int p = 0; p < 4; p++) {
            int row = b_row + p * 64;
            CPA16(sb + A_BYTES + row * 80 + b_kc * 16, Bt + (size_t)(col0 + row) * K + b_kc * 8);
        }
        CPC();
    }
    for (int kt = 0; kt < KITERS; kt++) {
        CPW0();
        __syncthreads();
        if (kt + 1 < KITERS) {
            const uint32_t st = sb + ((kt + 1) & 1) * STG_B;
            const int k0 = (kt + 1) << 5;
            #pragma unroll
            for (int p = 0; p < 2; p++) {
                int kc = a_kc + p * 2;
                CPA16(st + a_row * 80 + kc * 16, A + (size_t)(row0 + a_row) * K + k0 + kc * 8);
            }
            #pragma unroll
            for (int p = 0; p < 4; p++) {
                int row = b_row + p * 64;
                CPA16(st + A_BYTES + row * 80 + b_kc * 16, Bt + (size_t)(col0 + row) * K + k0 + b_kc * 8);
            }
            CPC();
        }
        const uint32_t* swA = (const uint32_t*)(sm + (kt & 1) * STG_B);
        const uint32_t* swB = (const uint32_t*)(sm + (kt & 1) * STG_B + A_BYTES);
        #pragma unroll
        for (int kk = 0; kk < 2; kk++) {
            uint32_t af[4][4], bf[8][2];
            const int kw = kk * 8 + tig;
            #pragma unroll
            for (int mi = 0; mi < 4; mi++) {
                int m = wm + mi * 16 + g;
                af[mi][0] = swA[m * 20 + kw];
                af[mi][1] = swA[(m + 8) * 20 + kw];
                af[mi][2] = swA[m * 20 + kw + 4];
                af[mi][3] = swA[(m + 8) * 20 + kw + 4];
            }
            #pragma unroll
            for (int nj = 0; nj < 8; nj++) {
                int n = wn + nj * 8 + g;
                bf[nj][0] = swB[n * 20 + kw];
                bf[nj][1] = swB[n * 20 + kw + 4];
            }
            #pragma unroll
            for (int mi = 0; mi < 4; mi++)
                #pragma unroll
                for (int nj = 0; nj < 8; nj++)
                    mma_f16(acc[mi][nj], af[mi], bf[nj]);
        }
    }
    #pragma unroll
    for (int mi = 0; mi < 4; mi++) {
        #pragma unroll
        for (int nj = 0; nj < 8; nj++) {
            int r = row0 + wm + mi * 16 + g;
            int c = col0 + wn + nj * 8 + tig * 2;
            *(float2*)(C + (size_t)r * N + c)       = make_float2(acc[mi][nj][0], acc[mi][nj][1]);
            *(float2*)(C + (size_t)(r + 8) * N + c) = make_float2(acc[mi][nj][2], acc[mi][nj][3]);
        }
    }
}

// ---------------- FiLM ----------------
__global__ __launch_bounds__(256) void film1_kernel(
    const float* __restrict__ cond, const float* __restrict__ w1, const float* __restrict__ b1)
{
    int j = blockIdx.x * 256 + threadIdx.x, i = blockIdx.y;
    const float* c = cond + i * COND_DIM;
    float acc = b1[j];
    #pragma unroll 4
    for (int k = 0; k < COND_DIM; k++) acc = fmaf(c[k], w1[k * TWO_DIM + j], acc);
    g_h1[i * TWO_DIM + j] = acc / (1.f + __expf(-acc));
}
__global__ __launch_bounds__(256) void film2_kernel(
    const float* __restrict__ w2, const float* __restrict__ b2)
{
    int j = blockIdx.x * 256 + threadIdx.x, i = blockIdx.y;
    const float* h = g_h1 + i * TWO_DIM;
    float acc = b2[j];
    #pragma unroll 4
    for (int k = 0; k < TWO_DIM; k++) acc = fmaf(h[k], w2[k * TWO_DIM + j], acc);
    g_gb[i * TWO_DIM + j] = acc;
}

// ---------------- LayerNorm + FiLM -> half ----------------
__global__ __launch_bounds__(256) void ln_film_kernel(const float* __restrict__ x)
{
    int row = blockIdx.x;
    int img = (row / NTOK) >> 5;
    const float4* xr = (const float4*)(x + (size_t)row * DIMX);
    int t = threadIdx.x;
    float4 v = xr[t];
    float s = v.x + v.y + v.z + v.w;
    float ss = v.x*v.x + v.y*v.y + v.z*v.z + v.w*v.w;
    __shared__ float rs_[8], rss[8];
    #pragma unroll
    for (int o = 16; o > 0; o >>= 1) {
        s += __shfl_down_sync(~0u, s, o); ss += __shfl_down_sync(~0u, ss, o);
    }
    int warp = t >> 5, lane = t & 31;
    if (lane == 0) { rs_[warp] = s; rss[warp] = ss; }
    __syncthreads();
    if (warp == 0) {
        s = (lane < 8) ? rs_[lane] : 0.f; ss = (lane < 8) ? rss[lane] : 0.f;
        #pragma unroll
        for (int o = 4; o > 0; o >>= 1) {
            s += __shfl_down_sync(~0u, s, o); ss += __shfl_down_sync(~0u, ss, o);
        }
        if (lane == 0) { rs_[0] = s; rss[0] = ss; }
    }
    __syncthreads();
    float mu = rs_[0] * (1.f / DIMX);
    float var = rss[0] * (1.f / DIMX) - mu * mu;
    float rstd = rsqrtf(var + 1e-5f);
    const float4* gam = (const float4*)(g_gb + (size_t)img * TWO_DIM);
    const float4* bet = (const float4*)(g_gb + (size_t)img * TWO_DIM + DIMX);
    float4 gv = gam[t], bv = bet[t];
    __half2 h0 = __floats2half2_rn(fmaf((v.x - mu) * rstd, gv.x, bv.x),
                                   fmaf((v.y - mu) * rstd, gv.y, bv.y));
    __half2 h1 = __floats2half2_rn(fmaf((v.z - mu) * rstd, gv.z, bv.z),
                                   fmaf((v.w - mu) * rstd, gv.w, bv.w));
    ((__half2*)(g_xnh + (size_t)row * DIMX))[t * 2]     = h0;
    ((__half2*)(g_xnh + (size_t)row * DIMX))[t * 2 + 1] = h1;
}

// ---------------- attention (flat-parallel) ----------------
__global__ __launch_bounds__(256) void attn_kernel(
    const float* __restrict__ q_gamma, const float* __restrict__ k_gamma,
    const float* __restrict__ rel_emb, const int* __restrict__ rel_idx)
{
    int b = blockIdx.x, h = blockIdx.y;
    __shared__ float qs[NTOK][DIM_HEAD], ks[NTOK][DIM_HEAD], vs[NTOK][DIM_HEAD];
    __shared__ float ps[NTOK][NTOK + 1], qg[DIM_HEAD], kg[DIM_HEAD];
    int t = threadIdx.x;
    if (t < DIM_HEAD) { qg[t] = q_gamma[h * DIM_HEAD + t]; kg[t] = k_gamma[h * DIM_HEAD + t]; }
    const float* base = g_qkv + (size_t)(b * NTOK) * (3 * DIMX) + h * DIM_HEAD;
    for (int e = t; e < NTOK * DIM_HEAD; e += 256) {
        int n = e >> 5, d = e & 31;
        const float* r = base + (size_t)n * (3 * DIMX);
        qs[n][d] = r[d]; ks[n][d] = r[DIMX + d]; vs[n][d] = r[2 * DIMX + d];
    }
    __syncthreads();
    if (t < NTOK) {
        float ss = 0.f;
        #pragma unroll
        for (int d = 0; d < DIM_HEAD; d++) { float v = qs[t][d]; ss += v * v; }
        float sc = 5.656854249f / fmaxf(sqrtf(ss), 1e-12f);
        #pragma unroll
        for (int d = 0; d < DIM_HEAD; d++) qs[t][d] *= sc * qg[d];
    } else if (t >= 128 && t < 128 + NTOK) {
        int r = t - 128;
        float ss = 0.f;
        #pragma unroll
        for (int d = 0; d < DIM_HEAD; d++) { float v = ks[r][d]; ss += v * v; }
        float sc = 5.656854249f / fmaxf(sqrtf(ss), 1e-12f);
        #pragma unroll
        for (int d = 0; d < DIM_HEAD; d++) ks[r][d] *= sc * kg[d];
    }
    __syncthreads();
    // sim + bias, all threads
    for (int e = t; e < NTOK * NTOK; e += 256) {
        int i = e / NTOK, j = e - i * NTOK;
        float s = 0.f;
        #pragma unroll
        for (int d = 0; d < DIM_HEAD; d++) s = fmaf(qs[i][d], ks[j][d], s);
        ps[i][j] = s + rel_emb[rel_idx[e] * HEADS + h];
    }
    __syncthreads();
    // softmax per row
    if (t < NTOK) {
        float mx = -1e30f;
        #pragma unroll 5
        for (int j = 0; j < NTOK; j++) mx = fmaxf(mx, ps[t][j]);
        float sum = 0.f;
        #pragma unroll 5
        for (int j = 0; j < NTOK; j++) { float p = __expf(ps[t][j] - mx); ps[t][j] = p; sum += p; }
        float inv = 1.f / sum;
        #pragma unroll 5
        for (int j = 0; j < NTOK; j++) ps[t][j] *= inv;
    }
    __syncthreads();
    // PV, all threads
    __half* outp = g_oh + (size_t)(b * NTOK) * DIMX + h * DIM_HEAD;
    for (int e = t; e < NTOK * DIM_HEAD; e += 256) {
        int i = e >> 5, d = e & 31;
        float a = 0.f;
        #pragma unroll 5
        for (int j = 0; j < NTOK; j++) a = fmaf(ps[i][j], vs[j][d], a);
        outp[(size_t)i * DIMX + d] = __float2half_rn(a);
    }
}

extern "C" void kernel_launch(void* const* d_in, const int* in_sizes, int n_in,
                              void* d_out, int out_size)
{
    const float* x       = (const float*)d_in[0];
    const float* cond    = (const float*)d_in[1];
    const float* fw1     = (const float*)d_in[2];
    const float* fb1     = (const float*)d_in[3];
    const float* fw2     = (const float*)d_in[4];
    const float* fb2     = (const float*)d_in[5];
    const float* wqkv    = (const float*)d_in[6];
    const float* qg      = (const float*)d_in[7];
    const float* kg      = (const float*)d_in[8];
    const float* rel_emb = (const float*)d_in[9];
    const float* wout    = (const float*)d_in[10];
    const int*   rel_idx = (const int*)d_in[11];
    float* out = (float*)d_out;

    __half *p_xnh, *p_oh, *p_wqkvT, *p_woutT;
    float *p_qkv;
    cudaGetSymbolAddress((void**)&p_xnh,   g_xnh);
    cudaGetSymbolAddress((void**)&p_qkv,   g_qkv);
    cudaGetSymbolAddress((void**)&p_oh,    g_oh);
    cudaGetSymbolAddress((void**)&p_wqkvT, g_wqkvT);
    cudaGetSymbolAddress((void**)&p_woutT, g_woutT);

    cudaFuncSetAttribute(hgemm_kernel, cudaFuncAttributeMaxDynamicSharedMemorySize, HG_SMEM);

    wtrans_kernel<<<dim3(3 * DIMX / 32, DIMX / 32), 256>>>(wqkv, p_wqkvT, DIMX, 3 * DIMX);
    wtrans_kernel<<<dim3(DIMX / 32, DIMX / 32), 256>>>(wout, p_woutT, DIMX, DIMX);

    film1_kernel<<<dim3(TWO_DIM / 256, B_IMG), 256>>>(cond, fw1, fb1);
    film2_kernel<<<dim3(TWO_DIM / 256, B_IMG), 256>>>(fw2, fb2);
    ln_film_kernel<<<M_TOK, 256>>>(x);

    hgemm_kernel<<<dim3(3 * DIMX / 256, M_TOK / 128), 256, HG_SMEM>>>(
        p_xnh, p_wqkvT, p_qkv, 3 * DIMX, DIMX);

    attn_kernel<<<dim3(B_TOT, HEADS), 256>>>(qg, kg, rel_emb, rel_idx);

    hgemm_kernel<<<dim3(DIMX / 256, M_TOK / 128), 256, HG_SMEM>>>(
        p_oh, p_woutT, out, DIMX, DIMX);
}